// round 8
// baseline (speedup 1.0000x reference)
#include <cuda_runtime.h>
#include <math.h>
#include <stdint.h>

#define BATCH 2
#define SEQ   2048
#define DIM   1024
#define NH    16
#define HD    64
#define MTOT  (BATCH*SEQ)   // 4096

// ---------------------------------------------------------------------------
// Scratch (allocation-free rule: __device__ globals)
// ---------------------------------------------------------------------------
__device__ float g_q[MTOT*DIM];
__device__ float g_k[MTOT*DIM];
__device__ float g_v[MTOT*DIM];
__device__ float g_a[MTOT*DIM];
// Transposed weights, stored as tf32 bit patterns: WT[n][k] = tf32(W[k][n])
__device__ float g_wqt[DIM*DIM];
__device__ float g_wkt[DIM*DIM];
__device__ float g_wvt[DIM*DIM];
__device__ float g_wot[DIM*DIM];

// ---------------------------------------------------------------------------
// Helpers
// ---------------------------------------------------------------------------
__device__ __forceinline__ uint32_t f2tf32(float f) {
    uint32_t u;
    asm("cvt.rna.tf32.f32 %0, %1;" : "=r"(u) : "f"(f));
    return u;
}
__device__ __forceinline__ uint32_t smem_u32(const void* p) {
    uint32_t a;
    asm("{ .reg .u64 t; cvta.to.shared.u64 t, %1; cvt.u32.u64 %0, t; }"
        : "=r"(a) : "l"(p));
    return a;
}

#define MMA_TF32(d, a, b) \
    asm volatile("mma.sync.aligned.m16n8k8.row.col.f32.tf32.tf32.f32 " \
        "{%0,%1,%2,%3}, {%4,%5,%6,%7}, {%8,%9}, {%0,%1,%2,%3};" \
        : "+f"((d)[0]), "+f"((d)[1]), "+f"((d)[2]), "+f"((d)[3]) \
        : "r"((a)[0]), "r"((a)[1]), "r"((a)[2]), "r"((a)[3]), \
          "r"((b)[0]), "r"((b)[1]))

#define CP_ASYNC16(dst_u32, src_ptr) \
    asm volatile("cp.async.cg.shared.global [%0], [%1], 16;" \
        :: "r"(dst_u32), "l"(src_ptr))
#define CP_COMMIT() asm volatile("cp.async.commit_group;" ::: "memory")
#define CP_WAIT0()  asm volatile("cp.async.wait_group 0;"  ::: "memory")
#define CP_WAIT1()  asm volatile("cp.async.wait_group 1;"  ::: "memory")

// ---------------------------------------------------------------------------
// Transpose + tf32-convert: W[K,N] fp32 -> WT[N,K] (tf32 bit patterns)
// ---------------------------------------------------------------------------
__global__ __launch_bounds__(256) void transpose_tf32_kernel(
    const float* __restrict__ W, float* __restrict__ WT)
{
    __shared__ float tile[32][33];
    const int k0 = blockIdx.y * 32;
    const int n0 = blockIdx.x * 32;
    const int tx = threadIdx.x;
    const int ty = threadIdx.y;
    #pragma unroll
    for (int i = ty; i < 32; i += 8)
        tile[i][tx] = W[(size_t)(k0 + i) * DIM + n0 + tx];
    __syncthreads();
    #pragma unroll
    for (int i = ty; i < 32; i += 8) {
        uint32_t u = f2tf32(tile[tx][i]);
        reinterpret_cast<uint32_t*>(WT)[(size_t)(n0 + i) * DIM + k0 + tx] = u;
    }
}

// ---------------------------------------------------------------------------
// tf32 tensor-core GEMM, cp.async 3-stage pipeline.
// CTA tile 128x128, BK=32, 8 warps (warp tile 64x32), m16n8k8.
// A raw fp32 in smem (cvt at fragment load); BT pre-rounded tf32 bits.
// ---------------------------------------------------------------------------
#define ASTRIDE      36
#define STAGE_FLOATS (128*ASTRIDE)          // one operand tile
#define BUF_FLOATS   (2*STAGE_FLOATS)       // A+B per stage
#define NSTG         3
#define GEMM_SMEM    (NSTG*BUF_FLOATS*4)    // 110592 B

__global__ __launch_bounds__(256) void gemm_tf32_kernel(
    const float* __restrict__ A, const float* __restrict__ BT,
    float* __restrict__ C, const float* __restrict__ bias)
{
    extern __shared__ float sm[];
    const int tid  = threadIdx.x;
    const int lane = tid & 31;
    const int wid  = tid >> 5;
    const int wm   = wid & 1;
    const int wn   = wid >> 1;
    const int bx   = blockIdx.x;
    const int by   = blockIdx.y;

    const int lr = tid >> 3;       // 0..31
    const int lq = tid & 7;        // 0..7

    const float* Ag = A  + (size_t)(by * 128 + lr) * DIM + lq * 4;
    const float* Bg = BT + (size_t)(bx * 128 + lr) * DIM + lq * 4;
    const uint32_t sbase = smem_u32(sm);
    const uint32_t soff  = (uint32_t)((lr * ASTRIDE + lq * 4) * 4);

    auto prefetch = [&](int s) {
        const uint32_t base = sbase + (uint32_t)(s % NSTG) * (BUF_FLOATS * 4);
        const float* Asrc = Ag + s * 32;
        const float* Bsrc = Bg + s * 32;
        #pragma unroll
        for (int j = 0; j < 4; j++) {
            const uint32_t d = base + soff + (uint32_t)(j * 32 * ASTRIDE * 4);
            CP_ASYNC16(d,                      Asrc + (size_t)j * 32 * DIM);
            CP_ASYNC16(d + STAGE_FLOATS * 4,   Bsrc + (size_t)j * 32 * DIM);
        }
        CP_COMMIT();
    };

    float c[4][4][4];
    #pragma unroll
    for (int i = 0; i < 4; i++)
        #pragma unroll
        for (int j = 0; j < 4; j++)
            #pragma unroll
            for (int k = 0; k < 4; k++)
                c[i][j][k] = 0.0f;

    prefetch(0);
    prefetch(1);

    const int NS = DIM / 32;   // 32 stages
    for (int s = 0; s < NS; s++) {
        if (s + 2 < NS) { CP_WAIT1(); } else { CP_WAIT0(); }
        __syncthreads();

        const float*    Af = sm + (s % NSTG) * BUF_FLOATS;
        const uint32_t* Bu = reinterpret_cast<const uint32_t*>(Af + STAGE_FLOATS);

        #pragma unroll
        for (int kk = 0; kk < 4; kk++) {
            uint32_t af[4][4], bf[4][2];
            const int col = kk * 8 + (lane & 3);
            const int r0  = wm * 64 + (lane >> 2);
            #pragma unroll
            for (int am = 0; am < 4; am++) {
                const float* p = Af + (r0 + am * 16) * ASTRIDE + col;
                af[am][0] = f2tf32(p[0]);
                af[am][1] = f2tf32(p[8 * ASTRIDE]);
                af[am][2] = f2tf32(p[4]);
                af[am][3] = f2tf32(p[8 * ASTRIDE + 4]);
            }
            #pragma unroll
            for (int bn = 0; bn < 4; bn++) {
                const uint32_t* p = Bu + (wn * 32 + bn * 8 + (lane >> 2)) * ASTRIDE + col;
                bf[bn][0] = p[0];
                bf[bn][1] = p[4];
            }
            #pragma unroll
            for (int am = 0; am < 4; am++)
                #pragma unroll
                for (int bn = 0; bn < 4; bn++)
                    MMA_TF32(c[am][bn], af[am], bf[bn]);
        }

        if (s + 2 < NS) prefetch(s + 2);
        __syncthreads();
    }

    const int rbase = by * 128 + wm * 64 + (lane >> 2);
    const int cbase = bx * 128 + wn * 32 + (lane & 3) * 2;
    #pragma unroll
    for (int am = 0; am < 4; am++) {
        #pragma unroll
        for (int bn = 0; bn < 4; bn++) {
            const int col = cbase + bn * 8;
            const int r0  = rbase + am * 16;
            float b0 = bias ? bias[col]     : 0.0f;
            float b1 = bias ? bias[col + 1] : 0.0f;
            *reinterpret_cast<float2*>(C + (size_t)r0 * DIM + col) =
                make_float2(c[am][bn][0] + b0, c[am][bn][1] + b1);
            *reinterpret_cast<float2*>(C + (size_t)(r0 + 8) * DIM + col) =
                make_float2(c[am][bn][2] + b0, c[am][bn][3] + b1);
        }
    }
}

// ---------------------------------------------------------------------------
// Tensor-core flash attention (tf32 mma.sync, causal) — exact R5 (proven).
// ---------------------------------------------------------------------------
#define AST 68
#define ATTN_SMEM (4*64*AST*4)   // 69632 B

__global__ __launch_bounds__(128, 2) void attn_tc_kernel(
    const float* __restrict__ Q, const float* __restrict__ K,
    const float* __restrict__ V, float* __restrict__ Oout)
{
    extern __shared__ float smem[];
    float* Ps  = smem;
    float* Khi = smem + 64 * AST;
    float* Klo = Khi + 64 * AST;
    float* Vs  = Klo + 64 * AST;

    const int b    = blockIdx.z;
    const int h    = blockIdx.y;
    const int q0   = (gridDim.x - 1 - blockIdx.x) * 64;
    const int tid  = threadIdx.x;
    const int wq   = tid >> 5;
    const int lane = tid & 31;
    const int gid  = lane >> 2;
    const int tig  = lane & 3;

    const float* Qg = Q + (size_t)b * SEQ * DIM + h * HD;
    const float* Kg = K + (size_t)b * SEQ * DIM + h * HD;
    const float* Vg = V + (size_t)b * SEQ * DIM + h * HD;

    #pragma unroll
    for (int i = 0; i < 8; i++) {
        int idx = tid + i * 128;
        int r = idx >> 4, c = (idx & 15) * 4;
        float4 v4 = *reinterpret_cast<const float4*>(Qg + (size_t)(q0 + r) * DIM + c);
        Ps[r * AST + c + 0] = v4.x * 0.125f;
        Ps[r * AST + c + 1] = v4.y * 0.125f;
        Ps[r * AST + c + 2] = v4.z * 0.125f;
        Ps[r * AST + c + 3] = v4.w * 0.125f;
    }
    __syncthreads();

    uint32_t qhi[8][4], qlo[8][4];
    {
        const int rr = wq * 16 + gid;
        #pragma unroll
        for (int kt = 0; kt < 8; kt++) {
            const int cc = kt * 8 + tig;
            float f[4];
            f[0] = Ps[rr * AST + cc];
            f[1] = Ps[(rr + 8) * AST + cc];
            f[2] = Ps[rr * AST + cc + 4];
            f[3] = Ps[(rr + 8) * AST + cc + 4];
            #pragma unroll
            for (int e = 0; e < 4; e++) {
                qhi[kt][e] = f2tf32(f[e]);
                qlo[kt][e] = f2tf32(f[e] - __uint_as_float(qhi[kt][e]));
            }
        }
    }

    float m0 = -1e30f, m1 = -1e30f, l0 = 0.0f, l1 = 0.0f;
    float o[8][4];
    #pragma unroll
    for (int nt = 0; nt < 8; nt++)
        #pragma unroll
        for (int e = 0; e < 4; e++) o[nt][e] = 0.0f;

    const int ntiles = (q0 >> 6) + 1;
    for (int t = 0; t < ntiles; t++) {
        const int kv0 = t * 64;
        __syncthreads();
        #pragma unroll
        for (int i = 0; i < 8; i++) {
            int idx = tid + i * 128;
            int r = idx >> 4, c = (idx & 15) * 4;
            float4 kk = *reinterpret_cast<const float4*>(Kg + (size_t)(kv0 + r) * DIM + c);
            float kv[4] = {kk.x, kk.y, kk.z, kk.w};
            #pragma unroll
            for (int e = 0; e < 4; e++) {
                uint32_t hi = f2tf32(kv[e]);
                Khi[r * AST + c + e] = __uint_as_float(hi);
                Klo[r * AST + c + e] = __uint_as_float(f2tf32(kv[e] - __uint_as_float(hi)));
            }
            float4 vv = *reinterpret_cast<const float4*>(Vg + (size_t)(kv0 + r) * DIM + c);
            Vs[r * AST + c + 0] = __uint_as_float(f2tf32(vv.x));
            Vs[r * AST + c + 1] = __uint_as_float(f2tf32(vv.y));
            Vs[r * AST + c + 2] = __uint_as_float(f2tf32(vv.z));
            Vs[r * AST + c + 3] = __uint_as_float(f2tf32(vv.w));
        }
        __syncthreads();

        float s[8][4];
        #pragma unroll
        for (int nt = 0; nt < 8; nt++)
            #pragma unroll
            for (int e = 0; e < 4; e++) s[nt][e] = 0.0f;

        #pragma unroll
        for (int kt = 0; kt < 8; kt++) {
            #pragma unroll
            for (int nt = 0; nt < 8; nt++) {
                const int boff = (nt * 8 + gid) * AST + kt * 8 + tig;
                uint32_t bh[2], bl[2];
                bh[0] = __float_as_uint(Khi[boff]);
                bh[1] = __float_as_uint(Khi[boff + 4]);
                bl[0] = __float_as_uint(Klo[boff]);
                bl[1] = __float_as_uint(Klo[boff + 4]);
                MMA_TF32(s[nt], qhi[kt], bh);
                MMA_TF32(s[nt], qlo[kt], bh);
                MMA_TF32(s[nt], qhi[kt], bl);
            }
        }

        const int r0g = q0 + wq * 16 + gid;
        const int r1g = r0g + 8;
        if (kv0 == q0) {
            #pragma unroll
            for (int nt = 0; nt < 8; nt++) {
                const int c0 = kv0 + nt * 8 + 2 * tig;
                if (c0     > r0g) s[nt][0] = -1e30f;
                if (c0 + 1 > r0g) s[nt][1] = -1e30f;
                if (c0     > r1g) s[nt][2] = -1e30f;
                if (c0 + 1 > r1g) s[nt][3] = -1e30f;
            }
        }

        float mx0 = -1e30f, mx1 = -1e30f;
        #pragma unroll
        for (int nt = 0; nt < 8; nt++) {
            mx0 = fmaxf(mx0, fmaxf(s[nt][0], s[nt][1]));
            mx1 = fmaxf(mx1, fmaxf(s[nt][2], s[nt][3]));
        }
        mx0 = fmaxf(mx0, __shfl_xor_sync(0xffffffffu, mx0, 1));
        mx0 = fmaxf(mx0, __shfl_xor_sync(0xffffffffu, mx0, 2));
        mx1 = fmaxf(mx1, __shfl_xor_sync(0xffffffffu, mx1, 1));
        mx1 = fmaxf(mx1, __shfl_xor_sync(0xffffffffu, mx1, 2));

        const float nm0 = fmaxf(m0, mx0);
        const float nm1 = fmaxf(m1, mx1);
        const float sc0 = __expf(m0 - nm0);
        const float sc1 = __expf(m1 - nm1);
        m0 = nm0; m1 = nm1;
        l0 *= sc0; l1 *= sc1;

        float sum0 = 0.0f, sum1 = 0.0f;
        float* pp = Ps + (wq * 16 + gid) * AST + 2 * tig;
        #pragma unroll
        for (int nt = 0; nt < 8; nt++) {
            float p00 = __expf(s[nt][0] - m0);
            float p01 = __expf(s[nt][1] - m0);
            float p10 = __expf(s[nt][2] - m1);
            float p11 = __expf(s[nt][3] - m1);
            sum0 += p00 + p01;
            sum1 += p10 + p11;
            pp[nt * 8]               = __uint_as_float(f2tf32(p00));
            pp[nt * 8 + 1]           = __uint_as_float(f2tf32(p01));
            pp[8 * AST + nt * 8]     = __uint_as_float(f2tf32(p10));
            pp[8 * AST + nt * 8 + 1] = __uint_as_float(f2tf32(p11));
            o[nt][0] *= sc0; o[nt][1] *= sc0;
            o[nt][2] *= sc1; o[nt][3] *= sc1;
        }
        sum0 += __shfl_xor_sync(0xffffffffu, sum0, 1);
        sum0 += __shfl_xor_sync(0xffffffffu, sum0, 2);
        sum1 += __shfl_xor_sync(0xffffffffu, sum1, 1);
        sum1 += __shfl_xor_sync(0xffffffffu, sum1, 2);
        l0 += sum0; l1 += sum1;

        __syncwarp();

        #pragma unroll
        for (int kt = 0; kt < 8; kt++) {
            uint32_t a[4];
            const float* ap = Ps + (wq * 16 + gid) * AST + kt * 8 + tig;
            a[0] = __float_as_uint(ap[0]);
            a[1] = __float_as_uint(ap[8 * AST]);
            a[2] = __float_as_uint(ap[4]);
            a[3] = __float_as_uint(ap[8 * AST + 4]);
            #pragma unroll
            for (int nt = 0; nt < 8; nt++) {
                const float* bp = Vs + (kt * 8 + tig) * AST + nt * 8 + gid;
                uint32_t bb[2];
                bb[0] = __float_as_uint(bp[0]);
                bb[1] = __float_as_uint(bp[4 * AST]);
                MMA_TF32(o[nt], a, bb);
            }
        }
        __syncwarp();
    }

    const float inv0 = 1.0f / l0;
    const float inv1 = 1.0f / l1;
    const int r0g = q0 + wq * 16 + gid;
    float* Og = Oout + (size_t)b * SEQ * DIM + h * HD;
    #pragma unroll
    for (int nt = 0; nt < 8; nt++) {
        const int col = nt * 8 + 2 * tig;
        float2 v0 = make_float2(o[nt][0] * inv0, o[nt][1] * inv0);
        float2 v1 = make_float2(o[nt][2] * inv1, o[nt][3] * inv1);
        *reinterpret_cast<float2*>(Og + (size_t)r0g * DIM + col)       = v0;
        *reinterpret_cast<float2*>(Og + (size_t)(r0g + 8) * DIM + col) = v1;
    }
}

// ---------------------------------------------------------------------------
// Launch (R5 structure: separate launches — fusion measured as a regression)
// ---------------------------------------------------------------------------
extern "C" void kernel_launch(void* const* d_in, const int* in_sizes, int n_in,
                              void* d_out, int out_size)
{
    const float* x  = (const float*)d_in[0];
    const float* Wq = (const float*)d_in[1];
    const float* Wk = (const float*)d_in[2];
    const float* Wv = (const float*)d_in[3];
    const float* Wo = (const float*)d_in[4];
    const float* bo = (const float*)d_in[5];
    float* out = (float*)d_out;

    float *qp, *kp, *vp, *ap, *wqt, *wkt, *wvt, *wot;
    cudaGetSymbolAddress((void**)&qp,  g_q);
    cudaGetSymbolAddress((void**)&kp,  g_k);
    cudaGetSymbolAddress((void**)&vp,  g_v);
    cudaGetSymbolAddress((void**)&ap,  g_a);
    cudaGetSymbolAddress((void**)&wqt, g_wqt);
    cudaGetSymbolAddress((void**)&wkt, g_wkt);
    cudaGetSymbolAddress((void**)&wvt, g_wvt);
    cudaGetSymbolAddress((void**)&wot, g_wot);

    cudaFuncSetAttribute(gemm_tf32_kernel,
                         cudaFuncAttributeMaxDynamicSharedMemorySize, GEMM_SMEM);
    cudaFuncSetAttribute(attn_tc_kernel,
                         cudaFuncAttributeMaxDynamicSharedMemorySize, ATTN_SMEM);

    dim3 wt_grid(DIM / 32, DIM / 32);
    dim3 wt_block(32, 8);
    transpose_tf32_kernel<<<wt_grid, wt_block>>>(Wq, wqt);
    transpose_tf32_kernel<<<wt_grid, wt_block>>>(Wk, wkt);
    transpose_tf32_kernel<<<wt_grid, wt_block>>>(Wv, wvt);
    transpose_tf32_kernel<<<wt_grid, wt_block>>>(Wo, wot);

    dim3 gemm_grid(DIM / 128, MTOT / 128);   // (8, 32)
    gemm_tf32_kernel<<<gemm_grid, 256, GEMM_SMEM>>>(x, wqt, qp, nullptr);
    gemm_tf32_kernel<<<gemm_grid, 256, GEMM_SMEM>>>(x, wkt, kp, nullptr);
    gemm_tf32_kernel<<<gemm_grid, 256, GEMM_SMEM>>>(x, wvt, vp, nullptr);

    dim3 attn_grid(SEQ / 64, NH, BATCH);     // (32, 16, 2)
    attn_tc_kernel<<<attn_grid, 128, ATTN_SMEM>>>(qp, kp, vp, ap);

    gemm_tf32_kernel<<<gemm_grid, 256, GEMM_SMEM>>>(ap, wot, out, bo);
}

// round 9
// speedup vs baseline: 1.4131x; 1.4131x over previous
#include <cuda_runtime.h>
#include <cuda_fp16.h>
#include <math.h>
#include <stdint.h>

#define BATCH 2
#define SEQ   2048
#define DIM   1024
#define NH    16
#define HD    64
#define MTOT  (BATCH*SEQ)   // 4096

// ---------------------------------------------------------------------------
// Scratch (allocation-free rule: __device__ globals)
// ---------------------------------------------------------------------------
__device__ float g_q[MTOT*DIM];
__device__ float g_k[MTOT*DIM];
__device__ float g_v[MTOT*DIM];
__device__ float g_a[MTOT*DIM];
// Transposed weights as fp16: WT[n][k] = fp16(W[k][n])
__device__ __half g_wqt[DIM*DIM];
__device__ __half g_wkt[DIM*DIM];
__device__ __half g_wvt[DIM*DIM];
__device__ __half g_wot[DIM*DIM];

// ---------------------------------------------------------------------------
// Helpers
// ---------------------------------------------------------------------------
__device__ __forceinline__ uint32_t f2tf32(float f) {
    uint32_t u;
    asm("cvt.rna.tf32.f32 %0, %1;" : "=r"(u) : "f"(f));
    return u;
}
__device__ __forceinline__ uint32_t h2bits(__half2 h) {
    return *reinterpret_cast<uint32_t*>(&h);
}

// fp16 mma: D(16x8,f32) += A(16x16,f16) * B(16x8,f16)
#define MMA_F16(d, a, b0, b1) \
    asm volatile("mma.sync.aligned.m16n8k16.row.col.f32.f16.f16.f32 " \
        "{%0,%1,%2,%3}, {%4,%5,%6,%7}, {%8,%9}, {%0,%1,%2,%3};" \
        : "+f"((d)[0]), "+f"((d)[1]), "+f"((d)[2]), "+f"((d)[3]) \
        : "r"((a)[0]), "r"((a)[1]), "r"((a)[2]), "r"((a)[3]), \
          "r"(b0), "r"(b1))

#define MMA_TF32(d, a, b) \
    asm volatile("mma.sync.aligned.m16n8k8.row.col.f32.tf32.tf32.f32 " \
        "{%0,%1,%2,%3}, {%4,%5,%6,%7}, {%8,%9}, {%0,%1,%2,%3};" \
        : "+f"((d)[0]), "+f"((d)[1]), "+f"((d)[2]), "+f"((d)[3]) \
        : "r"((a)[0]), "r"((a)[1]), "r"((a)[2]), "r"((a)[3]), \
          "r"((b)[0]), "r"((b)[1]))

// ---------------------------------------------------------------------------
// Transpose + fp16-convert: W[K,N] fp32 -> WT[N,K] fp16
// ---------------------------------------------------------------------------
__global__ __launch_bounds__(256) void transpose_f16_kernel(
    const float* __restrict__ W, __half* __restrict__ WT)
{
    __shared__ float tile[32][33];
    const int k0 = blockIdx.y * 32;
    const int n0 = blockIdx.x * 32;
    const int tx = threadIdx.x;
    const int ty = threadIdx.y;
    #pragma unroll
    for (int i = ty; i < 32; i += 8)
        tile[i][tx] = W[(size_t)(k0 + i) * DIM + n0 + tx];
    __syncthreads();
    #pragma unroll
    for (int i = ty; i < 32; i += 8)
        WT[(size_t)(n0 + i) * DIM + k0 + tx] = __float2half_rn(tile[tx][i]);
}

// ---------------------------------------------------------------------------
// fp16 tensor-core GEMM: C[4096,1024] = A @ B (+bias).
// CTA 128x128, BK=32, 8 warps (64x32 warp tile), m16n8k16, register prefetch,
// double-buffered smem. A fp32 gmem -> fp16 at stage store; BT fp16 in gmem.
// Smem rows stride 72 halves (36 words) -> fragment loads conflict-free.
// ---------------------------------------------------------------------------
#define HSTR 72                                // halves per smem row
#define STAGE_WORDS (128*36)                   // per operand (uint32 words)
#define BUF_WORDS   (2*STAGE_WORDS)            // A+B per stage
#define GEMM_SMEM   (2*BUF_WORDS*4)            // 73728 B

__global__ __launch_bounds__(256) void gemm_f16_kernel(
    const float* __restrict__ A, const __half* __restrict__ BT,
    float* __restrict__ C, const float* __restrict__ bias)
{
    extern __shared__ uint32_t smw[];
    const int tid  = threadIdx.x;
    const int lane = tid & 31;
    const int wid  = tid >> 5;
    const int wm   = wid & 1;
    const int wn   = wid >> 1;
    const int bx   = blockIdx.x;
    const int by   = blockIdx.y;
    const int gid  = lane >> 2;
    const int tig  = lane & 3;

    // A gmem: 128 rows x 32 fp32 per stage; thread: row=tid>>3, seg=tid&7 (4 floats)
    const int alr = tid >> 3, alq = tid & 7;
    // B gmem: 128 rows x 32 fp16 per stage; thread covers uint4 (8 halves):
    //   idx = tid + i*256 (i<2): row = idx>>2, seg = idx&3
    const float*  Ag = A  + (size_t)(by * 128 + alr) * DIM + alq * 4;
    const __half* Bg = BT + (size_t)(bx * 128) * DIM;

    float c[4][4][4];
    #pragma unroll
    for (int i = 0; i < 4; i++)
        #pragma unroll
        for (int j = 0; j < 4; j++)
            #pragma unroll
            for (int k = 0; k < 4; k++)
                c[i][j][k] = 0.0f;

    float4 pa[4];
    uint4  pb[2];
    auto gload = [&](int s) {
        #pragma unroll
        for (int j = 0; j < 4; j++)
            pa[j] = *reinterpret_cast<const float4*>(Ag + s * 32 + (size_t)j * 32 * DIM);
        #pragma unroll
        for (int i = 0; i < 2; i++) {
            int idx = tid + i * 256;
            int row = idx >> 2, seg = idx & 3;
            pb[i] = *reinterpret_cast<const uint4*>(Bg + (size_t)row * DIM + s * 32 + seg * 8);
        }
    };
    auto store_stage = [&](int b) {
        uint32_t* As = smw + b * BUF_WORDS;
        uint32_t* Bs = As + STAGE_WORDS;
        #pragma unroll
        for (int j = 0; j < 4; j++) {
            uint32_t u0 = h2bits(__floats2half2_rn(pa[j].x, pa[j].y));
            uint32_t u1 = h2bits(__floats2half2_rn(pa[j].z, pa[j].w));
            *reinterpret_cast<uint2*>(As + (alr + 32 * j) * 36 + alq * 2) = make_uint2(u0, u1);
        }
        #pragma unroll
        for (int i = 0; i < 2; i++) {
            int idx = tid + i * 256;
            int row = idx >> 2, seg = idx & 3;
            *reinterpret_cast<uint4*>(Bs + row * 36 + seg * 4) = pb[i];
        }
    };

    gload(0);
    store_stage(0);
    __syncthreads();

    const int NS = DIM / 32;
    for (int s = 0; s < NS; s++) {
        const int cur = s & 1;
        if (s + 1 < NS) gload(s + 1);

        const uint32_t* Au = smw + cur * BUF_WORDS;
        const uint32_t* Bu = Au + STAGE_WORDS;
        const int r0 = wm * 64 + gid;

        #pragma unroll
        for (int kk = 0; kk < 2; kk++) {
            uint32_t af[4][4], bf[4][2];
            const int ko = kk * 8 + tig;
            #pragma unroll
            for (int am = 0; am < 4; am++) {
                const uint32_t* p = Au + (r0 + am * 16) * 36 + ko;
                af[am][0] = p[0];
                af[am][1] = p[8 * 36];
                af[am][2] = p[4];
                af[am][3] = p[8 * 36 + 4];
            }
            #pragma unroll
            for (int bn = 0; bn < 4; bn++) {
                const uint32_t* p = Bu + (wn * 32 + bn * 8 + gid) * 36 + ko;
                bf[bn][0] = p[0];
                bf[bn][1] = p[4];
            }
            #pragma unroll
            for (int am = 0; am < 4; am++)
                #pragma unroll
                for (int bn = 0; bn < 4; bn++)
                    MMA_F16(c[am][bn], af[am], bf[bn][0], bf[bn][1]);
        }

        if (s + 1 < NS) {
            store_stage(1 - cur);
            __syncthreads();
        }
    }

    const int rbase = by * 128 + wm * 64 + gid;
    const int cbase = bx * 128 + wn * 32 + tig * 2;
    #pragma unroll
    for (int am = 0; am < 4; am++) {
        #pragma unroll
        for (int bn = 0; bn < 4; bn++) {
            const int col = cbase + bn * 8;
            const int r0  = rbase + am * 16;
            float b0 = bias ? bias[col]     : 0.0f;
            float b1 = bias ? bias[col + 1] : 0.0f;
            *reinterpret_cast<float2*>(C + (size_t)r0 * DIM + col) =
                make_float2(c[am][bn][0] + b0, c[am][bn][1] + b1);
            *reinterpret_cast<float2*>(C + (size_t)(r0 + 8) * DIM + col) =
                make_float2(c[am][bn][2] + b0, c[am][bn][3] + b1);
        }
    }
}

// ---------------------------------------------------------------------------
// Tensor-core flash attention (causal). QK^T: 3-term fp16 hi/lo split
// (m16n8k16, 2x rate, ~exact). PV: tf32 single-pass (proven R5 path).
// 128 threads = 4 warps, 64 q rows. kv tiles of 64.
// ---------------------------------------------------------------------------
#define AST 68
// Ps 64x68 f32 | Khi 64x36 words | Klo 64x36 words | Vs 64x68 f32
#define ATTN_SMEM ((64*AST + 64*36 + 64*36 + 64*AST)*4)   // 53248 B

__global__ __launch_bounds__(128, 2) void attn_tc_kernel(
    const float* __restrict__ Q, const float* __restrict__ K,
    const float* __restrict__ V, float* __restrict__ Oout)
{
    extern __shared__ float smem[];
    float*    Ps   = smem;                       // Q (prologue) then P (tf32 bits)
    uint32_t* KhiU = reinterpret_cast<uint32_t*>(smem + 64 * AST);
    uint32_t* KloU = KhiU + 64 * 36;
    float*    Vs   = reinterpret_cast<float*>(KloU + 64 * 36);

    const int b    = blockIdx.z;
    const int h    = blockIdx.y;
    const int q0   = (gridDim.x - 1 - blockIdx.x) * 64;
    const int tid  = threadIdx.x;
    const int wq   = tid >> 5;
    const int lane = tid & 31;
    const int gid  = lane >> 2;
    const int tig  = lane & 3;

    const float* Qg = Q + (size_t)b * SEQ * DIM + h * HD;
    const float* Kg = K + (size_t)b * SEQ * DIM + h * HD;
    const float* Vg = V + (size_t)b * SEQ * DIM + h * HD;

    // ---- Prologue: Q tile (scaled) -> smem fp32
    #pragma unroll
    for (int i = 0; i < 8; i++) {
        int idx = tid + i * 128;
        int r = idx >> 4, c = (idx & 15) * 4;
        float4 v4 = *reinterpret_cast<const float4*>(Qg + (size_t)(q0 + r) * DIM + c);
        Ps[r * AST + c + 0] = v4.x * 0.125f;
        Ps[r * AST + c + 1] = v4.y * 0.125f;
        Ps[r * AST + c + 2] = v4.z * 0.125f;
        Ps[r * AST + c + 3] = v4.w * 0.125f;
    }
    __syncthreads();

    // ---- Q fragments: fp16 hi/lo, m16n8k16 A-layout, kt = k16 tile (0..3)
    uint32_t qhi[4][4], qlo[4][4];
    {
        const int rr = wq * 16 + gid;
        #pragma unroll
        for (int kt = 0; kt < 4; kt++) {
            const int c0 = kt * 16 + 2 * tig;
            const int rc[4][2] = {{rr, c0}, {rr + 8, c0}, {rr, c0 + 8}, {rr + 8, c0 + 8}};
            #pragma unroll
            for (int e = 0; e < 4; e++) {
                float x0 = Ps[rc[e][0] * AST + rc[e][1]];
                float x1 = Ps[rc[e][0] * AST + rc[e][1] + 1];
                __half2 hh = __floats2half2_rn(x0, x1);
                float2  hf = __half22float2(hh);
                qhi[kt][e] = h2bits(hh);
                qlo[kt][e] = h2bits(__floats2half2_rn(x0 - hf.x, x1 - hf.y));
            }
        }
    }

    float m0 = -1e30f, m1 = -1e30f, l0 = 0.0f, l1 = 0.0f;
    float o[8][4];
    #pragma unroll
    for (int nt = 0; nt < 8; nt++)
        #pragma unroll
        for (int e = 0; e < 4; e++) o[nt][e] = 0.0f;

    const int ntiles = (q0 >> 6) + 1;
    for (int t = 0; t < ntiles; t++) {
        const int kv0 = t * 64;
        __syncthreads();
        // ---- Load K (fp16 hi/lo) and V (tf32 fp32) tiles
        #pragma unroll
        for (int i = 0; i < 8; i++) {
            int idx = tid + i * 128;
            int r = idx >> 4, cseg = idx & 15;
            int c = cseg * 4;
            float4 kk = *reinterpret_cast<const float4*>(Kg + (size_t)(kv0 + r) * DIM + c);
            __half2 h01 = __floats2half2_rn(kk.x, kk.y);
            __half2 h23 = __floats2half2_rn(kk.z, kk.w);
            float2 f01 = __half22float2(h01), f23 = __half22float2(h23);
            __half2 l01 = __floats2half2_rn(kk.x - f01.x, kk.y - f01.y);
            __half2 l23 = __floats2half2_rn(kk.z - f23.x, kk.w - f23.y);
            *reinterpret_cast<uint2*>(KhiU + r * 36 + cseg * 2) =
                make_uint2(h2bits(h01), h2bits(h23));
            *reinterpret_cast<uint2*>(KloU + r * 36 + cseg * 2) =
                make_uint2(h2bits(l01), h2bits(l23));

            float4 vv = *reinterpret_cast<const float4*>(Vg + (size_t)(kv0 + r) * DIM + c);
            Vs[r * AST + c + 0] = __uint_as_float(f2tf32(vv.x));
            Vs[r * AST + c + 1] = __uint_as_float(f2tf32(vv.y));
            Vs[r * AST + c + 2] = __uint_as_float(f2tf32(vv.z));
            Vs[r * AST + c + 3] = __uint_as_float(f2tf32(vv.w));
        }
        __syncthreads();

        // ---- S = Q @ K^T  (3-term fp16)
        float s[8][4];
        #pragma unroll
        for (int nt = 0; nt < 8; nt++)
            #pragma unroll
            for (int e = 0; e < 4; e++) s[nt][e] = 0.0f;

        #pragma unroll
        for (int kt = 0; kt < 4; kt++) {
            #pragma unroll
            for (int nt = 0; nt < 8; nt++) {
                const int boff = (nt * 8 + gid) * 36 + kt * 8 + tig;
                uint32_t bh0 = KhiU[boff], bh1 = KhiU[boff + 4];
                uint32_t bl0 = KloU[boff], bl1 = KloU[boff + 4];
                MMA_F16(s[nt], qhi[kt], bh0, bh1);
                MMA_F16(s[nt], qlo[kt], bh0, bh1);
                MMA_F16(s[nt], qhi[kt], bl0, bl1);
            }
        }

        const int r0g = q0 + wq * 16 + gid;
        const int r1g = r0g + 8;
        if (kv0 == q0) {
            #pragma unroll
            for (int nt = 0; nt < 8; nt++) {
                const int c0 = kv0 + nt * 8 + 2 * tig;
                if (c0     > r0g) s[nt][0] = -1e30f;
                if (c0 + 1 > r0g) s[nt][1] = -1e30f;
                if (c0     > r1g) s[nt][2] = -1e30f;
                if (c0 + 1 > r1g) s[nt][3] = -1e30f;
            }
        }

        // ---- Online softmax
        float mx0 = -1e30f, mx1 = -1e30f;
        #pragma unroll
        for (int nt = 0; nt < 8; nt++) {
            mx0 = fmaxf(mx0, fmaxf(s[nt][0], s[nt][1]));
            mx1 = fmaxf(mx1, fmaxf(s[nt][2], s[nt][3]));
        }
        mx0 = fmaxf(mx0, __shfl_xor_sync(0xffffffffu, mx0, 1));
        mx0 = fmaxf(mx0, __shfl_xor_sync(0xffffffffu, mx0, 2));
        mx1 = fmaxf(mx1, __shfl_xor_sync(0xffffffffu, mx1, 1));
        mx1 = fmaxf(mx1, __shfl_xor_sync(0xffffffffu, mx1, 2));

        const float nm0 = fmaxf(m0, mx0);
        const float nm1 = fmaxf(m1, mx1);
        const float sc0 = __expf(m0 - nm0);
        const float sc1 = __expf(m1 - nm1);
        m0 = nm0; m1 = nm1;
        l0 *= sc0; l1 *= sc1;

        float sum0 = 0.0f, sum1 = 0.0f;
        float* pp = Ps + (wq * 16 + gid) * AST + 2 * tig;
        #pragma unroll
        for (int nt = 0; nt < 8; nt++) {
            float p00 = __expf(s[nt][0] - m0);
            float p01 = __expf(s[nt][1] - m0);
            float p10 = __expf(s[nt][2] - m1);
            float p11 = __expf(s[nt][3] - m1);
            sum0 += p00 + p01;
            sum1 += p10 + p11;
            pp[nt * 8]               = __uint_as_float(f2tf32(p00));
            pp[nt * 8 + 1]           = __uint_as_float(f2tf32(p01));
            pp[8 * AST + nt * 8]     = __uint_as_float(f2tf32(p10));
            pp[8 * AST + nt * 8 + 1] = __uint_as_float(f2tf32(p11));
            o[nt][0] *= sc0; o[nt][1] *= sc0;
            o[nt][2] *= sc1; o[nt][3] *= sc1;
        }
        sum0 += __shfl_xor_sync(0xffffffffu, sum0, 1);
        sum0 += __shfl_xor_sync(0xffffffffu, sum0, 2);
        sum1 += __shfl_xor_sync(0xffffffffu, sum1, 1);
        sum1 += __shfl_xor_sync(0xffffffffu, sum1, 2);
        l0 += sum0; l1 += sum1;

        __syncwarp();

        // ---- O += P @ V  (tf32, proven path)
        #pragma unroll
        for (int kt = 0; kt < 8; kt++) {
            uint32_t a[4];
            const float* ap = Ps + (wq * 16 + gid) * AST + kt * 8 + tig;
            a[0] = __float_as_uint(ap[0]);
            a[1] = __float_as_uint(ap[8 * AST]);
            a[2] = __float_as_uint(ap[4]);
            a[3] = __float_as_uint(ap[8 * AST + 4]);
            #pragma unroll
            for (int nt = 0; nt < 8; nt++) {
                const float* bp = Vs + (kt * 8 + tig) * AST + nt * 8 + gid;
                uint32_t bb[2];
                bb[0] = __float_as_uint(bp[0]);
                bb[1] = __float_as_uint(bp[4 * AST]);
                MMA_TF32(o[nt], a, bb);
            }
        }
        __syncwarp();
    }

    const float inv0 = 1.0f / l0;
    const float inv1 = 1.0f / l1;
    const int r0g = q0 + wq * 16 + gid;
    float* Og = Oout + (size_t)b * SEQ * DIM + h * HD;
    #pragma unroll
    for (int nt = 0; nt < 8; nt++) {
        const int col = nt * 8 + 2 * tig;
        float2 v0 = make_float2(o[nt][0] * inv0, o[nt][1] * inv0);
        float2 v1 = make_float2(o[nt][2] * inv1, o[nt][3] * inv1);
        *reinterpret_cast<float2*>(Og + (size_t)r0g * DIM + col)       = v0;
        *reinterpret_cast<float2*>(Og + (size_t)(r0g + 8) * DIM + col) = v1;
    }
}

// ---------------------------------------------------------------------------
// Launch (R5 structure)
// ---------------------------------------------------------------------------
extern "C" void kernel_launch(void* const* d_in, const int* in_sizes, int n_in,
                              void* d_out, int out_size)
{
    const float* x  = (const float*)d_in[0];
    const float* Wq = (const float*)d_in[1];
    const float* Wk = (const float*)d_in[2];
    const float* Wv = (const float*)d_in[3];
    const float* Wo = (const float*)d_in[4];
    const float* bo = (const float*)d_in[5];
    float* out = (float*)d_out;

    float *qp, *kp, *vp, *ap;
    __half *wqt, *wkt, *wvt, *wot;
    cudaGetSymbolAddress((void**)&qp,  g_q);
    cudaGetSymbolAddress((void**)&kp,  g_k);
    cudaGetSymbolAddress((void**)&vp,  g_v);
    cudaGetSymbolAddress((void**)&ap,  g_a);
    cudaGetSymbolAddress((void**)&wqt, g_wqt);
    cudaGetSymbolAddress((void**)&wkt, g_wkt);
    cudaGetSymbolAddress((void**)&wvt, g_wvt);
    cudaGetSymbolAddress((void**)&wot, g_wot);

    cudaFuncSetAttribute(gemm_f16_kernel,
                         cudaFuncAttributeMaxDynamicSharedMemorySize, GEMM_SMEM);
    cudaFuncSetAttribute(attn_tc_kernel,
                         cudaFuncAttributeMaxDynamicSharedMemorySize, ATTN_SMEM);

    dim3 wt_grid(DIM / 32, DIM / 32);
    dim3 wt_block(32, 8);
    transpose_f16_kernel<<<wt_grid, wt_block>>>(Wq, wqt);
    transpose_f16_kernel<<<wt_grid, wt_block>>>(Wk, wkt);
    transpose_f16_kernel<<<wt_grid, wt_block>>>(Wv, wvt);
    transpose_f16_kernel<<<wt_grid, wt_block>>>(Wo, wot);

    dim3 gemm_grid(DIM / 128, MTOT / 128);   // (8, 32)
    gemm_f16_kernel<<<gemm_grid, 256, GEMM_SMEM>>>(x, wqt, qp, nullptr);
    gemm_f16_kernel<<<gemm_grid, 256, GEMM_SMEM>>>(x, wkt, kp, nullptr);
    gemm_f16_kernel<<<gemm_grid, 256, GEMM_SMEM>>>(x, wvt, vp, nullptr);

    dim3 attn_grid(SEQ / 64, NH, BATCH);     // (32, 16, 2)
    attn_tc_kernel<<<attn_grid, 128, ATTN_SMEM>>>(qp, kp, vp, ap);

    gemm_f16_kernel<<<gemm_grid, 256, GEMM_SMEM>>>(ap, wot, out, bo);
}

// round 10
// speedup vs baseline: 1.7246x; 1.2204x over previous
#include <cuda_runtime.h>
#include <cuda_fp16.h>
#include <math.h>
#include <stdint.h>

#define BATCH 2
#define SEQ   2048
#define DIM   1024
#define NH    16
#define HD    64
#define MTOT  (BATCH*SEQ)   // 4096

// ---------------------------------------------------------------------------
// Scratch (allocation-free rule: __device__ globals)
// ---------------------------------------------------------------------------
__device__ float g_q[MTOT*DIM];
__device__ float g_k[MTOT*DIM];
__device__ float g_v[MTOT*DIM];
__device__ float g_a[MTOT*DIM];
// Transposed weights as fp16: WT[n][k] = fp16(W[k][n])
__device__ __half g_wqt[DIM*DIM];
__device__ __half g_wkt[DIM*DIM];
__device__ __half g_wvt[DIM*DIM];
__device__ __half g_wot[DIM*DIM];

// ---------------------------------------------------------------------------
// Helpers
// ---------------------------------------------------------------------------
__device__ __forceinline__ uint32_t h2bits(__half2 h) {
    return *reinterpret_cast<uint32_t*>(&h);
}

// fp16 mma: D(16x8,f32) += A(16x16,f16) * B(16x8,f16)
#define MMA_F16(d, a, b0, b1) \
    asm volatile("mma.sync.aligned.m16n8k16.row.col.f32.f16.f16.f32 " \
        "{%0,%1,%2,%3}, {%4,%5,%6,%7}, {%8,%9}, {%0,%1,%2,%3};" \
        : "+f"((d)[0]), "+f"((d)[1]), "+f"((d)[2]), "+f"((d)[3]) \
        : "r"((a)[0]), "r"((a)[1]), "r"((a)[2]), "r"((a)[3]), \
          "r"(b0), "r"(b1))

// ---------------------------------------------------------------------------
// Transpose + fp16-convert: W[K,N] fp32 -> WT[N,K] fp16
// ---------------------------------------------------------------------------
__global__ __launch_bounds__(256) void transpose_f16_kernel(
    const float* __restrict__ W, __half* __restrict__ WT)
{
    __shared__ float tile[32][33];
    const int k0 = blockIdx.y * 32;
    const int n0 = blockIdx.x * 32;
    const int tx = threadIdx.x;
    const int ty = threadIdx.y;
    #pragma unroll
    for (int i = ty; i < 32; i += 8)
        tile[i][tx] = W[(size_t)(k0 + i) * DIM + n0 + tx];
    __syncthreads();
    #pragma unroll
    for (int i = ty; i < 32; i += 8)
        WT[(size_t)(n0 + i) * DIM + k0 + tx] = __float2half_rn(tile[tx][i]);
}

// ---------------------------------------------------------------------------
// fp16 tensor-core GEMM (exact R9, proven): C[4096,1024] = A @ B (+bias).
// ---------------------------------------------------------------------------
#define STAGE_WORDS (128*36)
#define BUF_WORDS   (2*STAGE_WORDS)
#define GEMM_SMEM   (2*BUF_WORDS*4)

__global__ __launch_bounds__(256) void gemm_f16_kernel(
    const float* __restrict__ A, const __half* __restrict__ BT,
    float* __restrict__ C, const float* __restrict__ bias)
{
    extern __shared__ uint32_t smw[];
    const int tid  = threadIdx.x;
    const int lane = tid & 31;
    const int wid  = tid >> 5;
    const int wm   = wid & 1;
    const int wn   = wid >> 1;
    const int bx   = blockIdx.x;
    const int by   = blockIdx.y;
    const int gid  = lane >> 2;
    const int tig  = lane & 3;

    const int alr = tid >> 3, alq = tid & 7;
    const float*  Ag = A  + (size_t)(by * 128 + alr) * DIM + alq * 4;
    const __half* Bg = BT + (size_t)(bx * 128) * DIM;

    float c[4][4][4];
    #pragma unroll
    for (int i = 0; i < 4; i++)
        #pragma unroll
        for (int j = 0; j < 4; j++)
            #pragma unroll
            for (int k = 0; k < 4; k++)
                c[i][j][k] = 0.0f;

    float4 pa[4];
    uint4  pb[2];
    auto gload = [&](int s) {
        #pragma unroll
        for (int j = 0; j < 4; j++)
            pa[j] = *reinterpret_cast<const float4*>(Ag + s * 32 + (size_t)j * 32 * DIM);
        #pragma unroll
        for (int i = 0; i < 2; i++) {
            int idx = tid + i * 256;
            int row = idx >> 2, seg = idx & 3;
            pb[i] = *reinterpret_cast<const uint4*>(Bg + (size_t)row * DIM + s * 32 + seg * 8);
        }
    };
    auto store_stage = [&](int b) {
        uint32_t* As = smw + b * BUF_WORDS;
        uint32_t* Bs = As + STAGE_WORDS;
        #pragma unroll
        for (int j = 0; j < 4; j++) {
            uint32_t u0 = h2bits(__floats2half2_rn(pa[j].x, pa[j].y));
            uint32_t u1 = h2bits(__floats2half2_rn(pa[j].z, pa[j].w));
            *reinterpret_cast<uint2*>(As + (alr + 32 * j) * 36 + alq * 2) = make_uint2(u0, u1);
        }
        #pragma unroll
        for (int i = 0; i < 2; i++) {
            int idx = tid + i * 256;
            int row = idx >> 2, seg = idx & 3;
            *reinterpret_cast<uint4*>(Bs + row * 36 + seg * 4) = pb[i];
        }
    };

    gload(0);
    store_stage(0);
    __syncthreads();

    const int NS = DIM / 32;
    for (int s = 0; s < NS; s++) {
        const int cur = s & 1;
        if (s + 1 < NS) gload(s + 1);

        const uint32_t* Au = smw + cur * BUF_WORDS;
        const uint32_t* Bu = Au + STAGE_WORDS;
        const int r0 = wm * 64 + gid;

        #pragma unroll
        for (int kk = 0; kk < 2; kk++) {
            uint32_t af[4][4], bf[4][2];
            const int ko = kk * 8 + tig;
            #pragma unroll
            for (int am = 0; am < 4; am++) {
                const uint32_t* p = Au + (r0 + am * 16) * 36 + ko;
                af[am][0] = p[0];
                af[am][1] = p[8 * 36];
                af[am][2] = p[4];
                af[am][3] = p[8 * 36 + 4];
            }
            #pragma unroll
            for (int bn = 0; bn < 4; bn++) {
                const uint32_t* p = Bu + (wn * 32 + bn * 8 + gid) * 36 + ko;
                bf[bn][0] = p[0];
                bf[bn][1] = p[4];
            }
            #pragma unroll
            for (int am = 0; am < 4; am++)
                #pragma unroll
                for (int bn = 0; bn < 4; bn++)
                    MMA_F16(c[am][bn], af[am], bf[bn][0], bf[bn][1]);
        }

        if (s + 1 < NS) {
            store_stage(1 - cur);
            __syncthreads();
        }
    }

    const int rbase = by * 128 + wm * 64 + gid;
    const int cbase = bx * 128 + wn * 32 + tig * 2;
    #pragma unroll
    for (int am = 0; am < 4; am++) {
        #pragma unroll
        for (int bn = 0; bn < 4; bn++) {
            const int col = cbase + bn * 8;
            const int r0  = rbase + am * 16;
            float b0 = bias ? bias[col]     : 0.0f;
            float b1 = bias ? bias[col + 1] : 0.0f;
            *reinterpret_cast<float2*>(C + (size_t)r0 * DIM + col) =
                make_float2(c[am][bn][0] + b0, c[am][bn][1] + b1);
            *reinterpret_cast<float2*>(C + (size_t)(r0 + 8) * DIM + col) =
                make_float2(c[am][bn][2] + b0, c[am][bn][3] + b1);
        }
    }
}

// ---------------------------------------------------------------------------
// Tensor-core flash attention v5 (causal), all-fp16 MMA.
//  QK^T: 3-term fp16 hi/lo (proven).  PV: fp16 m16n8k16 (NEW — same mantissa
//  as tf32, so error-neutral, at 2x MMA rate and half the LDS).
//  P packed half2 (stride 36 wds, reads bank=4*gid+tig: conflict-free).
//  V packed half2 cross-row (stride 72 wds, reads bank=8*tig+gid: c-free).
// 128 threads = 4 warps, 64 q rows. kv tiles of 64.
// ---------------------------------------------------------------------------
#define AST 68
// Qs [64][68]f (prologue; aliased by PpW [64][36]w) | Khi[64][36]w | Klo | Vp[32][72]w
#define ATTN_SMEM ((64*AST + 64*36 + 64*36 + 32*72)*4)   // 45056 B

__global__ __launch_bounds__(128, 3) void attn_tc_kernel(
    const float* __restrict__ Q, const float* __restrict__ K,
    const float* __restrict__ V, float* __restrict__ Oout)
{
    extern __shared__ float smem[];
    float*    Qs   = smem;                                   // prologue only
    uint32_t* PpW  = reinterpret_cast<uint32_t*>(smem);      // aliases Qs
    uint32_t* KhiU = reinterpret_cast<uint32_t*>(smem + 64 * AST);
    uint32_t* KloU = KhiU + 64 * 36;
    uint32_t* VpW  = KloU + 64 * 36;                         // [32][72]

    const int b    = blockIdx.z;
    const int h    = blockIdx.y;
    const int q0   = (gridDim.x - 1 - blockIdx.x) * 64;      // heavy first
    const int tid  = threadIdx.x;
    const int wq   = tid >> 5;
    const int lane = tid & 31;
    const int gid  = lane >> 2;
    const int tig  = lane & 3;

    const float* Qg = Q + (size_t)b * SEQ * DIM + h * HD;
    const float* Kg = K + (size_t)b * SEQ * DIM + h * HD;
    const float* Vg = V + (size_t)b * SEQ * DIM + h * HD;

    // ---- Prologue: Q tile (scaled) -> smem fp32
    #pragma unroll
    for (int i = 0; i < 8; i++) {
        int idx = tid + i * 128;
        int r = idx >> 4, c = (idx & 15) * 4;
        float4 v4 = *reinterpret_cast<const float4*>(Qg + (size_t)(q0 + r) * DIM + c);
        Qs[r * AST + c + 0] = v4.x * 0.125f;
        Qs[r * AST + c + 1] = v4.y * 0.125f;
        Qs[r * AST + c + 2] = v4.z * 0.125f;
        Qs[r * AST + c + 3] = v4.w * 0.125f;
    }
    __syncthreads();

    // ---- Q fragments: fp16 hi/lo, m16n8k16 A-layout
    uint32_t qhi[4][4], qlo[4][4];
    {
        const int rr = wq * 16 + gid;
        #pragma unroll
        for (int kt = 0; kt < 4; kt++) {
            const int c0 = kt * 16 + 2 * tig;
            const int rc[4][2] = {{rr, c0}, {rr + 8, c0}, {rr, c0 + 8}, {rr + 8, c0 + 8}};
            #pragma unroll
            for (int e = 0; e < 4; e++) {
                float x0 = Qs[rc[e][0] * AST + rc[e][1]];
                float x1 = Qs[rc[e][0] * AST + rc[e][1] + 1];
                __half2 hh = __floats2half2_rn(x0, x1);
                float2  hf = __half22float2(hh);
                qhi[kt][e] = h2bits(hh);
                qlo[kt][e] = h2bits(__floats2half2_rn(x0 - hf.x, x1 - hf.y));
            }
        }
    }
    __syncthreads();   // everyone done reading Qs before PpW overwrites it

    float m0 = -1e30f, m1 = -1e30f, l0 = 0.0f, l1 = 0.0f;
    float o[8][4];
    #pragma unroll
    for (int nt = 0; nt < 8; nt++)
        #pragma unroll
        for (int e = 0; e < 4; e++) o[nt][e] = 0.0f;

    const int ntiles = (q0 >> 6) + 1;
    for (int t = 0; t < ntiles; t++) {
        const int kv0 = t * 64;
        __syncthreads();
        // ---- K tile: fp16 hi/lo packed pairs along dim
        #pragma unroll
        for (int i = 0; i < 8; i++) {
            int idx = tid + i * 128;
            int r = idx >> 4, cseg = idx & 15;
            float4 kk = *reinterpret_cast<const float4*>(
                Kg + (size_t)(kv0 + r) * DIM + cseg * 4);
            __half2 h01 = __floats2half2_rn(kk.x, kk.y);
            __half2 h23 = __floats2half2_rn(kk.z, kk.w);
            float2 f01 = __half22float2(h01), f23 = __half22float2(h23);
            __half2 l01 = __floats2half2_rn(kk.x - f01.x, kk.y - f01.y);
            __half2 l23 = __floats2half2_rn(kk.z - f23.x, kk.w - f23.y);
            *reinterpret_cast<uint2*>(KhiU + r * 36 + cseg * 2) =
                make_uint2(h2bits(h01), h2bits(h23));
            *reinterpret_cast<uint2*>(KloU + r * 36 + cseg * 2) =
                make_uint2(h2bits(l01), h2bits(l23));
        }
        // ---- V tile: fp16 packed cross-row pairs (VpW[p][d] = {V[2p][d],V[2p+1][d]})
        #pragma unroll
        for (int i = 0; i < 4; i++) {
            int idx = tid + i * 128;            // 0..511
            int p = idx >> 4, cseg = idx & 15;
            const float* vr = Vg + (size_t)(kv0 + 2 * p) * DIM + cseg * 4;
            float4 v0 = *reinterpret_cast<const float4*>(vr);
            float4 v1 = *reinterpret_cast<const float4*>(vr + DIM);
            uint4 w;
            w.x = h2bits(__floats2half2_rn(v0.x, v1.x));
            w.y = h2bits(__floats2half2_rn(v0.y, v1.y));
            w.z = h2bits(__floats2half2_rn(v0.z, v1.z));
            w.w = h2bits(__floats2half2_rn(v0.w, v1.w));
            *reinterpret_cast<uint4*>(VpW + p * 72 + cseg * 4) = w;
        }
        __syncthreads();

        // ---- S = Q @ K^T  (3-term fp16)
        float s[8][4];
        #pragma unroll
        for (int nt = 0; nt < 8; nt++)
            #pragma unroll
            for (int e = 0; e < 4; e++) s[nt][e] = 0.0f;

        #pragma unroll
        for (int kt = 0; kt < 4; kt++) {
            #pragma unroll
            for (int nt = 0; nt < 8; nt++) {
                const int boff = (nt * 8 + gid) * 36 + kt * 8 + tig;
                uint32_t bh0 = KhiU[boff], bh1 = KhiU[boff + 4];
                uint32_t bl0 = KloU[boff], bl1 = KloU[boff + 4];
                MMA_F16(s[nt], qhi[kt], bh0, bh1);
                MMA_F16(s[nt], qlo[kt], bh0, bh1);
                MMA_F16(s[nt], qhi[kt], bl0, bl1);
            }
        }

        const int r0g = q0 + wq * 16 + gid;
        const int r1g = r0g + 8;
        if (kv0 == q0) {
            #pragma unroll
            for (int nt = 0; nt < 8; nt++) {
                const int c0 = kv0 + nt * 8 + 2 * tig;
                if (c0     > r0g) s[nt][0] = -1e30f;
                if (c0 + 1 > r0g) s[nt][1] = -1e30f;
                if (c0     > r1g) s[nt][2] = -1e30f;
                if (c0 + 1 > r1g) s[nt][3] = -1e30f;
            }
        }

        // ---- Online softmax
        float mx0 = -1e30f, mx1 = -1e30f;
        #pragma unroll
        for (int nt = 0; nt < 8; nt++) {
            mx0 = fmaxf(mx0, fmaxf(s[nt][0], s[nt][1]));
            mx1 = fmaxf(mx1, fmaxf(s[nt][2], s[nt][3]));
        }
        mx0 = fmaxf(mx0, __shfl_xor_sync(0xffffffffu, mx0, 1));
        mx0 = fmaxf(mx0, __shfl_xor_sync(0xffffffffu, mx0, 2));
        mx1 = fmaxf(mx1, __shfl_xor_sync(0xffffffffu, mx1, 1));
        mx1 = fmaxf(mx1, __shfl_xor_sync(0xffffffffu, mx1, 2));

        const float nm0 = fmaxf(m0, mx0);
        const float nm1 = fmaxf(m1, mx1);
        const float sc0 = __expf(m0 - nm0);
        const float sc1 = __expf(m1 - nm1);
        m0 = nm0; m1 = nm1;
        l0 *= sc0; l1 *= sc1;

        float sum0 = 0.0f, sum1 = 0.0f;
        const int prow = wq * 16 + gid;
        #pragma unroll
        for (int nt = 0; nt < 8; nt++) {
            float p00 = __expf(s[nt][0] - m0);
            float p01 = __expf(s[nt][1] - m0);
            float p10 = __expf(s[nt][2] - m1);
            float p11 = __expf(s[nt][3] - m1);
            sum0 += p00 + p01;
            sum1 += p10 + p11;
            PpW[prow * 36 + nt * 4 + tig]       = h2bits(__floats2half2_rn(p00, p01));
            PpW[(prow + 8) * 36 + nt * 4 + tig] = h2bits(__floats2half2_rn(p10, p11));
            o[nt][0] *= sc0; o[nt][1] *= sc0;
            o[nt][2] *= sc1; o[nt][3] *= sc1;
        }
        sum0 += __shfl_xor_sync(0xffffffffu, sum0, 1);
        sum0 += __shfl_xor_sync(0xffffffffu, sum0, 2);
        sum1 += __shfl_xor_sync(0xffffffffu, sum1, 1);
        sum1 += __shfl_xor_sync(0xffffffffu, sum1, 2);
        l0 += sum0; l1 += sum1;

        __syncwarp();

        // ---- O += P @ V  (fp16 m16n8k16)
        #pragma unroll
        for (int kt = 0; kt < 4; kt++) {
            uint32_t a[4];
            a[0] = PpW[prow * 36 + kt * 8 + tig];
            a[1] = PpW[(prow + 8) * 36 + kt * 8 + tig];
            a[2] = PpW[prow * 36 + kt * 8 + 4 + tig];
            a[3] = PpW[(prow + 8) * 36 + kt * 8 + 4 + tig];
            #pragma unroll
            for (int nt = 0; nt < 8; nt++) {
                uint32_t b0 = VpW[(kt * 8 + tig) * 72 + nt * 8 + gid];
                uint32_t b1 = VpW[(kt * 8 + 4 + tig) * 72 + nt * 8 + gid];
                MMA_F16(o[nt], a, b0, b1);
            }
        }
        __syncwarp();
    }

    const float inv0 = 1.0f / l0;
    const float inv1 = 1.0f / l1;
    const int r0g = q0 + wq * 16 + gid;
    float* Og = Oout + (size_t)b * SEQ * DIM + h * HD;
    #pragma unroll
    for (int nt = 0; nt < 8; nt++) {
        const int col = nt * 8 + 2 * tig;
        float2 v0 = make_float2(o[nt][0] * inv0, o[nt][1] * inv0);
        float2 v1 = make_float2(o[nt][2] * inv1, o[nt][3] * inv1);
        *reinterpret_cast<float2*>(Og + (size_t)r0g * DIM + col)       = v0;
        *reinterpret_cast<float2*>(Og + (size_t)(r0g + 8) * DIM + col) = v1;
    }
}

// ---------------------------------------------------------------------------
// Launch (R5/R9 structure)
// ---------------------------------------------------------------------------
extern "C" void kernel_launch(void* const* d_in, const int* in_sizes, int n_in,
                              void* d_out, int out_size)
{
    const float* x  = (const float*)d_in[0];
    const float* Wq = (const float*)d_in[1];
    const float* Wk = (const float*)d_in[2];
    const float* Wv = (const float*)d_in[3];
    const float* Wo = (const float*)d_in[4];
    const float* bo = (const float*)d_in[5];
    float* out = (float*)d_out;

    float *qp, *kp, *vp, *ap;
    __half *wqt, *wkt, *wvt, *wot;
    cudaGetSymbolAddress((void**)&qp,  g_q);
    cudaGetSymbolAddress((void**)&kp,  g_k);
    cudaGetSymbolAddress((void**)&vp,  g_v);
    cudaGetSymbolAddress((void**)&ap,  g_a);
    cudaGetSymbolAddress((void**)&wqt, g_wqt);
    cudaGetSymbolAddress((void**)&wkt, g_wkt);
    cudaGetSymbolAddress((void**)&wvt, g_wvt);
    cudaGetSymbolAddress((void**)&wot, g_wot);

    cudaFuncSetAttribute(gemm_f16_kernel,
                         cudaFuncAttributeMaxDynamicSharedMemorySize, GEMM_SMEM);
    cudaFuncSetAttribute(attn_tc_kernel,
                         cudaFuncAttributeMaxDynamicSharedMemorySize, ATTN_SMEM);

    dim3 wt_grid(DIM / 32, DIM / 32);
    dim3 wt_block(32, 8);
    transpose_f16_kernel<<<wt_grid, wt_block>>>(Wq, wqt);
    transpose_f16_kernel<<<wt_grid, wt_block>>>(Wk, wkt);
    transpose_f16_kernel<<<wt_grid, wt_block>>>(Wv, wvt);
    transpose_f16_kernel<<<wt_grid, wt_block>>>(Wo, wot);

    dim3 gemm_grid(DIM / 128, MTOT / 128);   // (8, 32)
    gemm_f16_kernel<<<gemm_grid, 256, GEMM_SMEM>>>(x, wqt, qp, nullptr);
    gemm_f16_kernel<<<gemm_grid, 256, GEMM_SMEM>>>(x, wkt, kp, nullptr);
    gemm_f16_kernel<<<gemm_grid, 256, GEMM_SMEM>>>(x, wvt, vp, nullptr);

    dim3 attn_grid(SEQ / 64, NH, BATCH);     // (32, 16, 2)
    attn_tc_kernel<<<attn_grid, 128, ATTN_SMEM>>>(qp, kp, vp, ap);

    gemm_f16_kernel<<<gemm_grid, 256, GEMM_SMEM>>>(ap, wot, out, bo);
}

// round 11
// speedup vs baseline: 1.8183x; 1.0543x over previous
#include <cuda_runtime.h>
#include <cuda_fp16.h>
#include <math.h>
#include <stdint.h>

#define BATCH 2
#define SEQ   2048
#define DIM   1024
#define NH    16
#define HD    64
#define MTOT  (BATCH*SEQ)   // 4096

// ---------------------------------------------------------------------------
// Scratch (allocation-free rule: __device__ globals)
// ---------------------------------------------------------------------------
__device__ float  g_a[MTOT*DIM];      // attention output (fp32)
__device__ __half g_qh[MTOT*DIM];     // Q, prescaled, fp16
__device__ __half g_khi[MTOT*DIM];    // K fp16 hi
__device__ __half g_klo[MTOT*DIM];    // K fp16 lo
__device__ __half g_vt[MTOT*DIM];     // V fp16, transposed: [b,h][d][s]
// Transposed weights as fp16: WT[n][k] = fp16(W[k][n])
__device__ __half g_wqt[DIM*DIM];
__device__ __half g_wkt[DIM*DIM];
__device__ __half g_wvt[DIM*DIM];
__device__ __half g_wot[DIM*DIM];

struct Ptr4 { const float* W[4]; __half* WT[4]; };

// ---------------------------------------------------------------------------
// Helpers
// ---------------------------------------------------------------------------
__device__ __forceinline__ uint32_t h2bits(__half2 h) {
    return *reinterpret_cast<uint32_t*>(&h);
}

// fp16 mma: D(16x8,f32) += A(16x16,f16) * B(16x8,f16)
#define MMA_F16(d, a, b0, b1) \
    asm volatile("mma.sync.aligned.m16n8k16.row.col.f32.f16.f16.f32 " \
        "{%0,%1,%2,%3}, {%4,%5,%6,%7}, {%8,%9}, {%0,%1,%2,%3};" \
        : "+f"((d)[0]), "+f"((d)[1]), "+f"((d)[2]), "+f"((d)[3]) \
        : "r"((a)[0]), "r"((a)[1]), "r"((a)[2]), "r"((a)[3]), \
          "r"(b0), "r"(b1))

// ---------------------------------------------------------------------------
// Fused transpose + fp16-convert: all 4 weights in one launch (z selects)
// ---------------------------------------------------------------------------
__global__ __launch_bounds__(256) void transpose_f16_kernel(Ptr4 p)
{
    __shared__ float tile[32][33];
    const float* W  = p.W[blockIdx.z];
    __half*      WT = p.WT[blockIdx.z];
    const int k0 = blockIdx.y * 32;
    const int n0 = blockIdx.x * 32;
    const int tx = threadIdx.x;
    const int ty = threadIdx.y;
    #pragma unroll
    for (int i = ty; i < 32; i += 8)
        tile[i][tx] = W[(size_t)(k0 + i) * DIM + n0 + tx];
    __syncthreads();
    #pragma unroll
    for (int i = ty; i < 32; i += 8)
        WT[(size_t)(n0 + i) * DIM + k0 + tx] = __float2half_rn(tile[tx][i]);
}

// ---------------------------------------------------------------------------
// fp16 tensor-core GEMM (R9 core, proven) with epilogue modes:
//   0: Cf = v + bias (fp32)          [output projection]
//   1: Ch = fp16(v * 0.125)          [Q, prescaled]
//   2: Ch = fp16_hi(v), Cl = fp16_lo [K, pre-split]
//   3: Ch = fp16(v), TRANSPOSED to [b,h][d][s]   [V]
// ---------------------------------------------------------------------------
#define STAGE_WORDS (128*36)
#define BUF_WORDS   (2*STAGE_WORDS)
#define GEMM_SMEM   (2*BUF_WORDS*4)

__global__ __launch_bounds__(256) void gemm_f16_kernel(
    const float* __restrict__ A, const __half* __restrict__ BT,
    float* __restrict__ Cf, __half* __restrict__ Ch, __half* __restrict__ Cl,
    const float* __restrict__ bias, int mode)
{
    extern __shared__ uint32_t smw[];
    const int tid  = threadIdx.x;
    const int lane = tid & 31;
    const int wid  = tid >> 5;
    const int wm   = wid & 1;
    const int wn   = wid >> 1;
    const int bx   = blockIdx.x;
    const int by   = blockIdx.y;
    const int gid  = lane >> 2;
    const int tig  = lane & 3;

    const int alr = tid >> 3, alq = tid & 7;
    const float*  Ag = A  + (size_t)(by * 128 + alr) * DIM + alq * 4;
    const __half* Bg = BT + (size_t)(bx * 128) * DIM;

    float c[4][4][4];
    #pragma unroll
    for (int i = 0; i < 4; i++)
        #pragma unroll
        for (int j = 0; j < 4; j++)
            #pragma unroll
            for (int k = 0; k < 4; k++)
                c[i][j][k] = 0.0f;

    float4 pa[4];
    uint4  pb[2];
    auto gload = [&](int s) {
        #pragma unroll
        for (int j = 0; j < 4; j++)
            pa[j] = *reinterpret_cast<const float4*>(Ag + s * 32 + (size_t)j * 32 * DIM);
        #pragma unroll
        for (int i = 0; i < 2; i++) {
            int idx = tid + i * 256;
            int row = idx >> 2, seg = idx & 3;
            pb[i] = *reinterpret_cast<const uint4*>(Bg + (size_t)row * DIM + s * 32 + seg * 8);
        }
    };
    auto store_stage = [&](int b) {
        uint32_t* As = smw + b * BUF_WORDS;
        uint32_t* Bs = As + STAGE_WORDS;
        #pragma unroll
        for (int j = 0; j < 4; j++) {
            uint32_t u0 = h2bits(__floats2half2_rn(pa[j].x, pa[j].y));
            uint32_t u1 = h2bits(__floats2half2_rn(pa[j].z, pa[j].w));
            *reinterpret_cast<uint2*>(As + (alr + 32 * j) * 36 + alq * 2) = make_uint2(u0, u1);
        }
        #pragma unroll
        for (int i = 0; i < 2; i++) {
            int idx = tid + i * 256;
            int row = idx >> 2, seg = idx & 3;
            *reinterpret_cast<uint4*>(Bs + row * 36 + seg * 4) = pb[i];
        }
    };

    gload(0);
    store_stage(0);
    __syncthreads();

    const int NS = DIM / 32;
    for (int s = 0; s < NS; s++) {
        const int cur = s & 1;
        if (s + 1 < NS) gload(s + 1);

        const uint32_t* Au = smw + cur * BUF_WORDS;
        const uint32_t* Bu = Au + STAGE_WORDS;
        const int r0 = wm * 64 + gid;

        #pragma unroll
        for (int kk = 0; kk < 2; kk++) {
            uint32_t af[4][4], bf[4][2];
            const int ko = kk * 8 + tig;
            #pragma unroll
            for (int am = 0; am < 4; am++) {
                const uint32_t* p = Au + (r0 + am * 16) * 36 + ko;
                af[am][0] = p[0];
                af[am][1] = p[8 * 36];
                af[am][2] = p[4];
                af[am][3] = p[8 * 36 + 4];
            }
            #pragma unroll
            for (int bn = 0; bn < 4; bn++) {
                const uint32_t* p = Bu + (wn * 32 + bn * 8 + gid) * 36 + ko;
                bf[bn][0] = p[0];
                bf[bn][1] = p[4];
            }
            #pragma unroll
            for (int am = 0; am < 4; am++)
                #pragma unroll
                for (int bn = 0; bn < 4; bn++)
                    MMA_F16(c[am][bn], af[am], bf[bn][0], bf[bn][1]);
        }

        if (s + 1 < NS) {
            store_stage(1 - cur);
            __syncthreads();
        }
    }

    const int rbase = by * 128 + wm * 64 + gid;
    const int cbase = bx * 128 + wn * 32 + tig * 2;
    #pragma unroll
    for (int am = 0; am < 4; am++) {
        #pragma unroll
        for (int bn = 0; bn < 4; bn++) {
            const int col = cbase + bn * 8;
            const int r0  = rbase + am * 16;
            const float v00 = c[am][bn][0], v01 = c[am][bn][1];
            const float v10 = c[am][bn][2], v11 = c[am][bn][3];
            if (mode == 0) {
                float b0 = bias[col], b1 = bias[col + 1];
                *reinterpret_cast<float2*>(Cf + (size_t)r0 * DIM + col) =
                    make_float2(v00 + b0, v01 + b1);
                *reinterpret_cast<float2*>(Cf + (size_t)(r0 + 8) * DIM + col) =
                    make_float2(v10 + b0, v11 + b1);
            } else if (mode == 1) {
                reinterpret_cast<uint32_t*>(Ch)[((size_t)r0 * DIM + col) >> 1] =
                    h2bits(__floats2half2_rn(v00 * 0.125f, v01 * 0.125f));
                reinterpret_cast<uint32_t*>(Ch)[((size_t)(r0 + 8) * DIM + col) >> 1] =
                    h2bits(__floats2half2_rn(v10 * 0.125f, v11 * 0.125f));
            } else if (mode == 2) {
                __half2 h0 = __floats2half2_rn(v00, v01);
                __half2 h1 = __floats2half2_rn(v10, v11);
                float2 f0 = __half22float2(h0), f1 = __half22float2(h1);
                reinterpret_cast<uint32_t*>(Ch)[((size_t)r0 * DIM + col) >> 1] = h2bits(h0);
                reinterpret_cast<uint32_t*>(Ch)[((size_t)(r0 + 8) * DIM + col) >> 1] = h2bits(h1);
                reinterpret_cast<uint32_t*>(Cl)[((size_t)r0 * DIM + col) >> 1] =
                    h2bits(__floats2half2_rn(v00 - f0.x, v01 - f0.y));
                reinterpret_cast<uint32_t*>(Cl)[((size_t)(r0 + 8) * DIM + col) >> 1] =
                    h2bits(__floats2half2_rn(v10 - f1.x, v11 - f1.y));
            } else {
                // V transposed: vt[(row>>11)*2097152 + colv*2048 + (row&2047)]
                const size_t bb = (size_t)(r0 >> 11) * 2097152;
                const int s0 = r0 & 2047;
                Ch[bb + (size_t)col * 2048 + s0]           = __float2half_rn(v00);
                Ch[bb + (size_t)(col + 1) * 2048 + s0]     = __float2half_rn(v01);
                Ch[bb + (size_t)col * 2048 + s0 + 8]       = __float2half_rn(v10);
                Ch[bb + (size_t)(col + 1) * 2048 + s0 + 8] = __float2half_rn(v11);
            }
        }
    }
}

// ---------------------------------------------------------------------------
// Tensor-core flash attention v6 (causal), all-fp16 MMA, pure-copy tiles.
//  QK^T: 2-term fp16 (qhi*khi + qhi*klo) — dropped qlo*khi term adds only
//  ~1.4e-4 absolute logit noise.  PV: fp16 (proven R10).
//  All operands pre-formatted by GEMM epilogues: tile loads are uint4 copies.
//  All smem arrays [64][36] words: fragment reads bank = 4*gid+tig, c-free.
// 128 threads = 4 warps, 64 q rows. kv tiles of 64.
// ---------------------------------------------------------------------------
#define ATTN_SMEM (4*64*36*4)    // 36864 B

__global__ __launch_bounds__(128, 4) void attn_tc_kernel(
    const __half* __restrict__ Qh, const __half* __restrict__ Khi,
    const __half* __restrict__ Klo, const __half* __restrict__ Vt,
    float* __restrict__ Oout)
{
    extern __shared__ uint32_t smw[];
    uint32_t* PpW  = smw;                    // [64][36]; holds Q tile in prologue
    uint32_t* KhiU = smw + 64 * 36;
    uint32_t* KloU = KhiU + 64 * 36;
    uint32_t* VpW  = KloU + 64 * 36;         // [64 d][36] (kv-pair words)

    const int b    = blockIdx.z;
    const int h    = blockIdx.y;
    const int q0   = (gridDim.x - 1 - blockIdx.x) * 64;   // heavy first
    const int tid  = threadIdx.x;
    const int wq   = tid >> 5;
    const int lane = tid & 31;
    const int gid  = lane >> 2;
    const int tig  = lane & 3;

    const __half* Qg  = Qh  + ((size_t)b * SEQ + q0) * DIM + h * HD;
    const __half* Khg = Khi + (size_t)b * SEQ * DIM + h * HD;
    const __half* Klg = Klo + (size_t)b * SEQ * DIM + h * HD;
    const __half* Vtg = Vt  + (size_t)(b * NH + h) * (HD * SEQ);

    // ---- Prologue: Q tile pure copy -> PpW region, then fragment extract
    #pragma unroll
    for (int i = 0; i < 4; i++) {
        int idx = tid + i * 128;
        int r = idx >> 3, seg = idx & 7;
        *reinterpret_cast<uint4*>(PpW + r * 36 + seg * 4) =
            *reinterpret_cast<const uint4*>(Qg + (size_t)r * DIM + seg * 8);
    }
    __syncthreads();

    uint32_t qh[4][4];
    {
        const int rr = wq * 16 + gid;
        #pragma unroll
        for (int kt = 0; kt < 4; kt++) {
            qh[kt][0] = PpW[rr * 36 + kt * 8 + tig];
            qh[kt][1] = PpW[(rr + 8) * 36 + kt * 8 + tig];
            qh[kt][2] = PpW[rr * 36 + kt * 8 + 4 + tig];
            qh[kt][3] = PpW[(rr + 8) * 36 + kt * 8 + 4 + tig];
        }
    }

    float m0 = -1e30f, m1 = -1e30f, l0 = 0.0f, l1 = 0.0f;
    float o[8][4];
    #pragma unroll
    for (int nt = 0; nt < 8; nt++)
        #pragma unroll
        for (int e = 0; e < 4; e++) o[nt][e] = 0.0f;

    const int ntiles = (q0 >> 6) + 1;
    for (int t = 0; t < ntiles; t++) {
        const int kv0 = t * 64;
        __syncthreads();
        // ---- Pure-copy tile loads: Khi, Klo ([kv r][d]), V ([d][kv])
        #pragma unroll
        for (int i = 0; i < 4; i++) {
            int idx = tid + i * 128;
            int r = idx >> 3, seg = idx & 7;
            *reinterpret_cast<uint4*>(KhiU + r * 36 + seg * 4) =
                *reinterpret_cast<const uint4*>(Khg + (size_t)(kv0 + r) * DIM + seg * 8);
            *reinterpret_cast<uint4*>(KloU + r * 36 + seg * 4) =
                *reinterpret_cast<const uint4*>(Klg + (size_t)(kv0 + r) * DIM + seg * 8);
            *reinterpret_cast<uint4*>(VpW + r * 36 + seg * 4) =
                *reinterpret_cast<const uint4*>(Vtg + (size_t)r * SEQ + kv0 + seg * 8);
        }
        __syncthreads();

        // ---- S = Q @ K^T  (2-term fp16)
        float s[8][4];
        #pragma unroll
        for (int nt = 0; nt < 8; nt++)
            #pragma unroll
            for (int e = 0; e < 4; e++) s[nt][e] = 0.0f;

        #pragma unroll
        for (int kt = 0; kt < 4; kt++) {
            #pragma unroll
            for (int nt = 0; nt < 8; nt++) {
                const int boff = (nt * 8 + gid) * 36 + kt * 8 + tig;
                uint32_t bh0 = KhiU[boff], bh1 = KhiU[boff + 4];
                uint32_t bl0 = KloU[boff], bl1 = KloU[boff + 4];
                MMA_F16(s[nt], qh[kt], bh0, bh1);
                MMA_F16(s[nt], qh[kt], bl0, bl1);
            }
        }

        const int r0g = q0 + wq * 16 + gid;
        const int r1g = r0g + 8;
        if (kv0 == q0) {
            #pragma unroll
            for (int nt = 0; nt < 8; nt++) {
                const int c0 = kv0 + nt * 8 + 2 * tig;
                if (c0     > r0g) s[nt][0] = -1e30f;
                if (c0 + 1 > r0g) s[nt][1] = -1e30f;
                if (c0     > r1g) s[nt][2] = -1e30f;
                if (c0 + 1 > r1g) s[nt][3] = -1e30f;
            }
        }

        // ---- Online softmax
        float mx0 = -1e30f, mx1 = -1e30f;
        #pragma unroll
        for (int nt = 0; nt < 8; nt++) {
            mx0 = fmaxf(mx0, fmaxf(s[nt][0], s[nt][1]));
            mx1 = fmaxf(mx1, fmaxf(s[nt][2], s[nt][3]));
        }
        mx0 = fmaxf(mx0, __shfl_xor_sync(0xffffffffu, mx0, 1));
        mx0 = fmaxf(mx0, __shfl_xor_sync(0xffffffffu, mx0, 2));
        mx1 = fmaxf(mx1, __shfl_xor_sync(0xffffffffu, mx1, 1));
        mx1 = fmaxf(mx1, __shfl_xor_sync(0xffffffffu, mx1, 2));

        const float nm0 = fmaxf(m0, mx0);
        const float nm1 = fmaxf(m1, mx1);
        const float sc0 = __expf(m0 - nm0);
        const float sc1 = __expf(m1 - nm1);
        m0 = nm0; m1 = nm1;
        l0 *= sc0; l1 *= sc1;

        float sum0 = 0.0f, sum1 = 0.0f;
        const int prow = wq * 16 + gid;
        #pragma unroll
        for (int nt = 0; nt < 8; nt++) {
            float p00 = __expf(s[nt][0] - m0);
            float p01 = __expf(s[nt][1] - m0);
            float p10 = __expf(s[nt][2] - m1);
            float p11 = __expf(s[nt][3] - m1);
            sum0 += p00 + p01;
            sum1 += p10 + p11;
            PpW[prow * 36 + nt * 4 + tig]       = h2bits(__floats2half2_rn(p00, p01));
            PpW[(prow + 8) * 36 + nt * 4 + tig] = h2bits(__floats2half2_rn(p10, p11));
            o[nt][0] *= sc0; o[nt][1] *= sc0;
            o[nt][2] *= sc1; o[nt][3] *= sc1;
        }
        sum0 += __shfl_xor_sync(0xffffffffu, sum0, 1);
        sum0 += __shfl_xor_sync(0xffffffffu, sum0, 2);
        sum1 += __shfl_xor_sync(0xffffffffu, sum1, 1);
        sum1 += __shfl_xor_sync(0xffffffffu, sum1, 2);
        l0 += sum0; l1 += sum1;

        __syncwarp();

        // ---- O += P @ V  (fp16; V tile is [d][kv-pair])
        #pragma unroll
        for (int kt = 0; kt < 4; kt++) {
            uint32_t a[4];
            a[0] = PpW[prow * 36 + kt * 8 + tig];
            a[1] = PpW[(prow + 8) * 36 + kt * 8 + tig];
            a[2] = PpW[prow * 36 + kt * 8 + 4 + tig];
            a[3] = PpW[(prow + 8) * 36 + kt * 8 + 4 + tig];
            #pragma unroll
            for (int nt = 0; nt < 8; nt++) {
                const int voff = (nt * 8 + gid) * 36 + kt * 8 + tig;
                MMA_F16(o[nt], a, VpW[voff], VpW[voff + 4]);
            }
        }
        __syncwarp();
    }

    const float inv0 = 1.0f / l0;
    const float inv1 = 1.0f / l1;
    const int r0g = q0 + wq * 16 + gid;
    float* Og = Oout + (size_t)b * SEQ * DIM + h * HD;
    #pragma unroll
    for (int nt = 0; nt < 8; nt++) {
        const int col = nt * 8 + 2 * tig;
        float2 v0 = make_float2(o[nt][0] * inv0, o[nt][1] * inv0);
        float2 v1 = make_float2(o[nt][2] * inv1, o[nt][3] * inv1);
        *reinterpret_cast<float2*>(Og + (size_t)r0g * DIM + col)       = v0;
        *reinterpret_cast<float2*>(Og + (size_t)(r0g + 8) * DIM + col) = v1;
    }
}

// ---------------------------------------------------------------------------
// Launch
// ---------------------------------------------------------------------------
extern "C" void kernel_launch(void* const* d_in, const int* in_sizes, int n_in,
                              void* d_out, int out_size)
{
    const float* x  = (const float*)d_in[0];
    const float* Wq = (const float*)d_in[1];
    const float* Wk = (const float*)d_in[2];
    const float* Wv = (const float*)d_in[3];
    const float* Wo = (const float*)d_in[4];
    const float* bo = (const float*)d_in[5];
    float* out = (float*)d_out;

    float *ap;
    __half *qh, *khi, *klo, *vt, *wqt, *wkt, *wvt, *wot;
    cudaGetSymbolAddress((void**)&ap,  g_a);
    cudaGetSymbolAddress((void**)&qh,  g_qh);
    cudaGetSymbolAddress((void**)&khi, g_khi);
    cudaGetSymbolAddress((void**)&klo, g_klo);
    cudaGetSymbolAddress((void**)&vt,  g_vt);
    cudaGetSymbolAddress((void**)&wqt, g_wqt);
    cudaGetSymbolAddress((void**)&wkt, g_wkt);
    cudaGetSymbolAddress((void**)&wvt, g_wvt);
    cudaGetSymbolAddress((void**)&wot, g_wot);

    cudaFuncSetAttribute(gemm_f16_kernel,
                         cudaFuncAttributeMaxDynamicSharedMemorySize, GEMM_SMEM);
    cudaFuncSetAttribute(attn_tc_kernel,
                         cudaFuncAttributeMaxDynamicSharedMemorySize, ATTN_SMEM);

    // 1) all 4 weight transposes in one launch
    Ptr4 tp;
    tp.W[0] = Wq;   tp.W[1] = Wk;   tp.W[2] = Wv;   tp.W[3] = Wo;
    tp.WT[0] = wqt; tp.WT[1] = wkt; tp.WT[2] = wvt; tp.WT[3] = wot;
    dim3 wt_grid(DIM / 32, DIM / 32, 4);
    dim3 wt_block(32, 8);
    transpose_f16_kernel<<<wt_grid, wt_block>>>(tp);

    // 2) Q/K/V projections with attention-ready epilogues
    dim3 gemm_grid(DIM / 128, MTOT / 128);   // (8, 32)
    gemm_f16_kernel<<<gemm_grid, 256, GEMM_SMEM>>>(x, wqt, nullptr, qh,  nullptr, nullptr, 1);
    gemm_f16_kernel<<<gemm_grid, 256, GEMM_SMEM>>>(x, wkt, nullptr, khi, klo,     nullptr, 2);
    gemm_f16_kernel<<<gemm_grid, 256, GEMM_SMEM>>>(x, wvt, nullptr, vt,  nullptr, nullptr, 3);

    // 3) attention (pure-copy tiles, 2-term QK, fp16 PV)
    dim3 attn_grid(SEQ / 64, NH, BATCH);     // (32, 16, 2)
    attn_tc_kernel<<<attn_grid, 128, ATTN_SMEM>>>(qh, khi, klo, vt, ap);

    // 4) output projection (+bias)
    gemm_f16_kernel<<<gemm_grid, 256, GEMM_SMEM>>>(ap, wot, out, nullptr, nullptr, bo, 0);
}